// round 17
// baseline (speedup 1.0000x reference)
#include <cuda_runtime.h>
#include <cuda_bf16.h>
#include <cstdint>

// Balloon-Windkessel BOLD, explicit Euler, T=1000 steps, B=16384 sims.
// R17 = R16 compute (bit-identical; rel_err 1.235969e-4) with ALL global
// memory moved to async bulk-DMA (scoreboard-free):
//  - theory: 20-LDG prefetch bursts alias the 6 HW scoreboard slots; the
//    counting SB makes each chunk's first consumers wait on the FRESH burst
//    (~577 cyc/chunk = ~29 cyc/step) - the op-count-invariant residual seen
//    in R7-R16.
//  - noise:  cp.async.bulk (global->smem) per 512B row-slice, mbarrier
//    completion, double-buffered; one acquire-wait per 20-step chunk.
//  - output: STS -> cp.async.bulk (smem->global) bulk_group per chunk;
//    STG(5-cyc issue) leaves the hot loop.
//  - compute stream, constants, geometry (128x128, 1 warp/SMSP) unchanged.

#define DT_C        0.01f
#define V0_C        0.02f
#define NOISE_AMP_C 0.01f
#define BATCH_C     16384
#define UC          20           // chunk steps
#define SIMS_PB     128          // sims per block (= threads per block)

// ---- Known benchmark parameters (checked at runtime, never assumed) ----
#define P_SIGMA 0.9f
#define P_MU    0.8f
#define P_LAMB  0.3f
#define P_BETA  0.9f
#define P_PSI   0.5f
#define P_PHI   2.0f
#define P_CHI   0.3f

#define FK_A0   (1.0f - DT_C * P_SIGMA)
#define FK_A1   (DT_C * NOISE_AMP_C)
#define FK_NA2  (-DT_C * P_MU)
#define FK_CVL  (DT_C / P_LAMB)
#define FK_C0   (V0_C * (P_PHI + P_PSI + P_CHI))
#define FK_C1   (V0_C * P_PHI)
#define FK_C2   (V0_C * P_PSI)
#define FK_C3   (V0_C * P_CHI)
#define FK_G0   1.0f
#define FK_G1   ((float)0.7441572118895505)
#define FK_G2   ((float)-0.2945498950265777)
#define FK_G3   ((float)0.0684745030)

// ---- async-DMA helpers ----
__device__ __forceinline__ uint32_t smem_u32(const void* p) {
    uint32_t a;
    asm("{ .reg .u64 t; cvta.to.shared.u64 t, %1; cvt.u32.u64 %0, t; }"
        : "=r"(a) : "l"(p));
    return a;
}
#define MBAR_INIT(m, c) \
    asm volatile("mbarrier.init.shared.b64 [%0], %1;" :: "r"(m), "r"(c) : "memory")
#define MBAR_EXPECT_TX(m, b) \
    asm volatile("mbarrier.arrive.expect_tx.shared.b64 _, [%0], %1;" :: "r"(m), "r"(b) : "memory")
#define MBAR_WAIT(m, ph) do {                                            \
    asm volatile(                                                        \
        "{\n\t.reg .pred P;\n\t"                                         \
        "W%=:\n\t"                                                       \
        "mbarrier.try_wait.parity.acquire.cta.shared::cta.b64 P, [%0], %1, 0x989680;\n\t" \
        "@P bra.uni D%=;\n\t"                                            \
        "bra.uni W%=;\n\t"                                               \
        "D%=:\n\t}"                                                      \
        :: "r"(m), "r"(ph) : "memory");                                  \
} while (0)
#define BULK_G2S(dst, src, sz, mbar) \
    asm volatile("cp.async.bulk.shared::cluster.global.mbarrier::complete_tx::bytes [%0], [%1], %2, [%3];" \
                 :: "r"(dst), "l"(src), "r"(sz), "r"(mbar) : "memory")
#define BULK_S2G(dst, src, sz) \
    asm volatile("cp.async.bulk.global.shared::cta.bulk_group [%0], [%1], %2;" \
                 :: "l"(dst), "r"(src), "r"(sz) : "memory")
#define BULK_COMMIT()  asm volatile("cp.async.bulk.commit_group;" ::: "memory")
#define BULK_WAIT(n)   asm volatile("cp.async.bulk.wait_group %0;" :: "n"(n) : "memory")
#define FENCE_ASYNC()  asm volatile("fence.proxy.async.shared::cta;" ::: "memory")

struct BWState {
    float s, f, v, q;
    float rv;    // running 1/v (Newton-refreshed)
    float b2u;   // -DT*mu*u  (staged)
    float fv;    // f - v     (staged)
    float qd;    // G - q     (staged)
};
struct BWConst {
    float a0, a1, na2, c_vl;
    float C0, C1, C2, C3;
    float g0, g1, g2, g3;
};

// One Euler step. Bit-identical to R16's bw_step.
template<bool FAST>
__device__ __forceinline__ float bw_step(BWState& st, const BWConst& C, float z)
{
    const float a0  = FAST ? FK_A0  : C.a0;
    const float a1  = FAST ? FK_A1  : C.a1;
    const float na2 = FAST ? FK_NA2 : C.na2;
    const float cvl = FAST ? FK_CVL : C.c_vl;
    const float C0  = FAST ? FK_C0  : C.C0;
    const float C1  = FAST ? FK_C1  : C.C1;
    const float C2  = FAST ? FK_C2  : C.C2;
    const float C3  = FAST ? FK_C3  : C.C3;
    const float g0  = FAST ? FK_G0  : C.g0;
    const float g1  = FAST ? FK_G1  : C.g1;
    const float g2  = FAST ? FK_G2  : C.g2;
    const float g3  = FAST ? FK_G3  : C.g3;

    const float s2 = fmaf(a0, st.s, fmaf(a1, z, st.b2u));
    const float f2 = fmaf(DT_C, st.s, st.f);
    const float v2 = fmaf(cvl, st.fv, st.v);
    const float q2 = fmaf(cvl, st.qd, st.q);

    const float tN  = fmaf(-v2, st.rv, 2.0f);
    const float rv2 = st.rv * tN;

    const float u   = f2 - 1.0f;
    const float u2  = u * u;
    const float p01 = fmaf(g1, u, g0);
    const float p23 = fmaf(g3, u, g2);
    const float G   = fmaf(u2, p23, p01);
    st.b2u = na2 * u;
    st.fv  = f2 - v2;
    st.qd  = G - q2;

    const float t0 = fmaf(-C3, v2, C0);
    const float t1 = fmaf(-C1, q2, t0);
    const float y  = fmaf(-C2 * q2, rv2, t1);

    st.s = s2; st.f = f2; st.v = v2; st.q = q2; st.rv = rv2;
    return y;
}

template<bool FAST>
__device__ __forceinline__ void run_pipeline(
    const BWConst& C, BWState& st,
    const float* __restrict__ noise, float* __restrict__ out,
    int T, int tid, int colbase,
    float (*sIn)[UC][SIMS_PB], float (*sOut)[UC][SIMS_PB],
    unsigned long long* mbar)
{
    const int nch = T / UC;
    const uint32_t mb0 = smem_u32(&mbar[0]);
    const uint32_t mb1 = smem_u32(&mbar[1]);
    const uint32_t ROWB = SIMS_PB * 4;           // 512 bytes per row-slice
    const uint32_t CHB  = UC * ROWB;             // bytes per chunk tile

    if (tid == 0) {
        MBAR_INIT(mb0, 1);
        MBAR_INIT(mb1, 1);
    }
    __syncthreads();

    // Prologue: kick chunks 0 and 1.
    if (tid == 0) {
        for (int k = 0; k < 2 && k < nch; k++) {
            const uint32_t mb = k ? mb1 : mb0;
            MBAR_EXPECT_TX(mb, CHB);
            const uint32_t sdst = smem_u32(&sIn[k][0][0]);
            for (int i = 0; i < UC; i++) {
                const float* src = noise + (size_t)(k * UC + i) * BATCH_C + colbase;
                BULK_G2S(sdst + i * ROWB, src, ROWB, mb);
            }
        }
    }

    for (int c = 0; c < nch; c++) {
        const int b  = c & 1;
        const uint32_t ph = (uint32_t)((c >> 1) & 1);
        const uint32_t mb = b ? mb1 : mb0;

        // Free this out-buffer: allow at most 1 outstanding store group.
        if (tid == 0) BULK_WAIT(1);
        __syncthreads();

        // Wait for this in-tile (acquire).
        MBAR_WAIT(mb, ph);

        // Compute 20 steps: smem in -> smem out. Bit-identical math to R16.
        #pragma unroll
        for (int i = 0; i < UC; i++) {
            const float z = sIn[b][i][tid];
            sOut[b][i][tid] = bw_step<FAST>(st, C, z);
        }
        __syncthreads();   // all reads of sIn[b] done; STS drained for DMA

        if (tid == 0) {
            // Stream this chunk's outputs to global as one bulk group.
            FENCE_ASYNC();
            const uint32_t ssrc = smem_u32(&sOut[b][0][0]);
            for (int i = 0; i < UC; i++) {
                float* dst = out + (size_t)(c * UC + i) * BATCH_C + colbase;
                BULK_S2G(dst, ssrc + i * ROWB, ROWB);
            }
            BULK_COMMIT();
            // Refill this in-buffer with chunk c+2.
            if (c + 2 < nch) {
                MBAR_EXPECT_TX(mb, CHB);
                const uint32_t sdst = smem_u32(&sIn[b][0][0]);
                for (int i = 0; i < UC; i++) {
                    const float* src = noise + (size_t)((c + 2) * UC + i) * BATCH_C + colbase;
                    BULK_G2S(sdst + i * ROWB, src, ROWB, mb);
                }
            }
        }
    }

    // Tail (T not divisible by UC): plain loads/stores.
    for (int t = nch * UC; t < T; t++) {
        const float z = noise[(size_t)t * BATCH_C + colbase + tid];
        out[(size_t)t * BATCH_C + colbase + tid] = bw_step<FAST>(st, C, z);
    }

    if (tid == 0) BULK_WAIT(0);   // flush all store groups before exit
}

__global__ __launch_bounds__(SIMS_PB, 1)
void bw_bold_kernel(const float* __restrict__ noise,
                    const float* __restrict__ sigma_p,
                    const float* __restrict__ mu_p,
                    const float* __restrict__ lamb_p,
                    const float* __restrict__ beta_p,
                    const float* __restrict__ psi_p,
                    const float* __restrict__ phi_p,
                    const float* __restrict__ chi_p,
                    float* __restrict__ out,
                    int T)
{
    __shared__ float sIn [2][UC][SIMS_PB];
    __shared__ float sOut[2][UC][SIMS_PB];
    __shared__ alignas(8) unsigned long long mbar[2];

    const int tid     = threadIdx.x;
    const int colbase = blockIdx.x * SIMS_PB;

    const float sigma = __ldg(sigma_p);
    const float mu    = __ldg(mu_p);
    const float lamb  = __ldg(lamb_p);
    const float beta  = __ldg(beta_p);
    const float psi   = __ldg(psi_p);
    const float phi   = __ldg(phi_p);
    const float chi   = __ldg(chi_p);

    const bool fast = (sigma == P_SIGMA) && (mu == P_MU) && (lamb == P_LAMB) &&
                      (beta == P_BETA) && (psi == P_PSI) && (phi == P_PHI) &&
                      (chi == P_CHI);

    BWConst C;
    C.a0   = 1.0f - DT_C * sigma;
    C.a1   = DT_C * NOISE_AMP_C;
    C.na2  = -DT_C * mu;
    C.c_vl = DT_C / lamb;
    C.C0   = V0_C * (phi + psi + chi);
    C.C1   = V0_C * phi;
    C.C2   = V0_C * psi;
    C.C3   = V0_C * chi;

    if (!fast) {
        // Generic path: runtime Taylor coefficients (double series).
        const double bd  = (double)beta;
        const double cc  = log(1.0 - bd);
        const double omb = 1.0 - bd;
        double a[5], A[5], e[5];
        a[0] = 0.0;
        #pragma unroll
        for (int k = 1; k < 5; k++) a[k] = (k & 1) ? -cc : cc;
        A[0] = 1.0;
        #pragma unroll
        for (int k = 0; k < 4; k++) {
            double sum = 0.0;
            #pragma unroll
            for (int j = 0; j <= k; j++) sum += (double)(j + 1) * a[j + 1] * A[k - j];
            A[k + 1] = sum / (double)(k + 1);
        }
        e[0] = 1.0 - omb * A[0];
        #pragma unroll
        for (int k = 1; k < 5; k++) e[k] = -omb * A[k];
        const double ibd = 1.0 / bd;
        C.g0 = (float)(e[0] * ibd);
        C.g1 = (float)((e[1] + e[0]) * ibd);
        C.g2 = (float)((e[2] + e[1]) * ibd);
        C.g3 = (float)((e[3] + e[2]) * ibd);
    } else {
        C.g0 = FK_G0; C.g1 = FK_G1; C.g2 = FK_G2; C.g3 = FK_G3;
    }

    BWState st;
    st.s = 0.0f; st.f = 1.0f; st.v = 1.0f; st.q = 1.0f;
    st.rv  = 1.0f;
    st.b2u = C.na2 * 0.0f;
    st.fv  = 0.0f;
    st.qd  = C.g0 - 1.0f;

    if (fast) run_pipeline<true >(C, st, noise, out, T, tid, colbase, sIn, sOut, mbar);
    else      run_pipeline<false>(C, st, noise, out, T, tid, colbase, sIn, sOut, mbar);
}

extern "C" void kernel_launch(void* const* d_in, const int* in_sizes, int n_in,
                              void* d_out, int out_size)
{
    const float* noise = (const float*)d_in[0];
    const int T = in_sizes[0] / BATCH_C;

    const int threads = SIMS_PB;
    const int blocks  = BATCH_C / SIMS_PB;   // 128 blocks x 128 thr = 1 warp/SMSP

    bw_bold_kernel<<<blocks, threads>>>(
        noise,
        (const float*)d_in[1], (const float*)d_in[2],
        (const float*)d_in[3], (const float*)d_in[4],
        (const float*)d_in[5], (const float*)d_in[6],
        (const float*)d_in[7],
        (float*)d_out, T);
}